// round 1
// baseline (speedup 1.0000x reference)
#include <cuda_runtime.h>
#include <math.h>

#define N_NODES 50000
#define N_EDGES 800000
#define F 128
#define TM 64
#define TK 32

// Scratch (allocation-free rule: __device__ globals)
__device__ float g_h[N_NODES * F];      // feat @ W_pool^T + b_pool
__device__ float g_agg[N_NODES * F];    // edge-aggregated messages
__device__ float g_wsum[N_NODES];
__device__ float g_deg[N_NODES];
__device__ float g_WpT[F * F];          // W_pool transposed: [k][c]
__device__ float g_WsT[F * F];          // W_self transposed: [k][c]

// ---------------------------------------------------------------------------
// Zero scratch accumulators (must run every launch: deterministic replays)
// ---------------------------------------------------------------------------
__global__ void zero_kernel() {
    int i = blockIdx.x * blockDim.x + threadIdx.x;
    if (i < N_NODES * F / 4)
        ((float4*)g_agg)[i] = make_float4(0.f, 0.f, 0.f, 0.f);
    if (i < N_NODES) {
        g_wsum[i] = 0.f;
        g_deg[i]  = 0.f;
    }
}

// ---------------------------------------------------------------------------
// Transpose both weight matrices once so the GEMM's SMEM staging is
// fully coalesced and bank-conflict-free.
// ---------------------------------------------------------------------------
__global__ void transpose_w(const float* __restrict__ Wp,
                            const float* __restrict__ Ws) {
    int i = blockIdx.x * blockDim.x + threadIdx.x;   // 16384
    if (i < F * F) {
        int c = i >> 7;          // 0..127
        int k = i & (F - 1);     // 0..127 (coalesced read along k)
        g_WpT[k * F + c] = Wp[c * F + k];
        g_WsT[k * F + c] = Ws[c * F + k];
    }
}

// ---------------------------------------------------------------------------
// Per-destination weight sum + degree
// ---------------------------------------------------------------------------
__global__ void degsum_kernel(const float* __restrict__ efeat,
                              const int* __restrict__ dst) {
    int e = blockIdx.x * blockDim.x + threadIdx.x;
    if (e < N_EDGES) {
        int d = dst[e];
        atomicAdd(&g_wsum[d], efeat[e]);
        atomicAdd(&g_deg[d], 1.0f);
    }
}

// ---------------------------------------------------------------------------
// Dual GEMM: h = feat @ Wp^T + bp  (to g_h),  out = feat @ Ws^T + bs (to d_out)
// Block = 256 threads, computes a 64x128 tile for BOTH outputs.
// Thread (tr,tc): rows tr*4..tr*4+3, cols {tc*4..tc*4+3} and {64+tc*4..+3}.
// ---------------------------------------------------------------------------
__global__ __launch_bounds__(256) void gemm_dual(const float* __restrict__ feat,
                                                 const float* __restrict__ bp,
                                                 const float* __restrict__ bs,
                                                 float* __restrict__ out) {
    __shared__ float As[TM][TK + 4];   // row stride 36 floats (16B aligned)
    __shared__ float Wps[TK][F];
    __shared__ float Wss[TK][F];

    int tid  = threadIdx.x;
    int row0 = blockIdx.x * TM;
    int tr   = tid >> 4;   // 0..15
    int tc   = tid & 15;   // 0..15

    float accP[4][8];
    float accS[4][8];
#pragma unroll
    for (int r = 0; r < 4; r++)
#pragma unroll
        for (int c = 0; c < 8; c++) { accP[r][c] = 0.f; accS[r][c] = 0.f; }

    for (int kt = 0; kt < F; kt += TK) {
        // Stage A tile: 64 rows x 32 k = 512 float4
#pragma unroll
        for (int j = 0; j < 2; j++) {
            int f4 = tid + j * 256;          // 0..511
            int r  = f4 >> 3;                // 0..63
            int k4 = f4 & 7;                 // 0..7
            int gr = row0 + r;
            float4 v = make_float4(0.f, 0.f, 0.f, 0.f);
            if (gr < N_NODES)
                v = *(const float4*)&feat[gr * F + kt + k4 * 4];
            *(float4*)&As[r][k4 * 4] = v;
        }
        // Stage W tiles: 32 x 128 = 1024 float4 each (coalesced, conflict-free)
#pragma unroll
        for (int j = 0; j < 4; j++) {
            int f4 = tid + j * 256;          // 0..1023
            int k  = f4 >> 5;                // 0..31
            int c4 = f4 & 31;                // 0..31
            *(float4*)&Wps[k][c4 * 4] = *(const float4*)&g_WpT[(kt + k) * F + c4 * 4];
            *(float4*)&Wss[k][c4 * 4] = *(const float4*)&g_WsT[(kt + k) * F + c4 * 4];
        }
        __syncthreads();

#pragma unroll
        for (int kk = 0; kk < TK; kk++) {
            float a[4];
#pragma unroll
            for (int r = 0; r < 4; r++) a[r] = As[tr * 4 + r][kk];
            float4 p0 = *(const float4*)&Wps[kk][tc * 4];
            float4 p1 = *(const float4*)&Wps[kk][64 + tc * 4];
            float4 s0 = *(const float4*)&Wss[kk][tc * 4];
            float4 s1 = *(const float4*)&Wss[kk][64 + tc * 4];
            float pv[8] = {p0.x, p0.y, p0.z, p0.w, p1.x, p1.y, p1.z, p1.w};
            float sv[8] = {s0.x, s0.y, s0.z, s0.w, s1.x, s1.y, s1.z, s1.w};
#pragma unroll
            for (int r = 0; r < 4; r++) {
#pragma unroll
                for (int c = 0; c < 8; c++) {
                    accP[r][c] = fmaf(a[r], pv[c], accP[r][c]);
                    accS[r][c] = fmaf(a[r], sv[c], accS[r][c]);
                }
            }
        }
        __syncthreads();
    }

    // Epilogue: add bias, vectorized stores
    int c0 = tc * 4;
    int c1 = 64 + tc * 4;
    float4 bpv0 = make_float4(bp[c0], bp[c0 + 1], bp[c0 + 2], bp[c0 + 3]);
    float4 bpv1 = make_float4(bp[c1], bp[c1 + 1], bp[c1 + 2], bp[c1 + 3]);
    float4 bsv0 = make_float4(bs[c0], bs[c0 + 1], bs[c0 + 2], bs[c0 + 3]);
    float4 bsv1 = make_float4(bs[c1], bs[c1 + 1], bs[c1 + 2], bs[c1 + 3]);
#pragma unroll
    for (int r = 0; r < 4; r++) {
        int gr = row0 + tr * 4 + r;
        if (gr < N_NODES) {
            float4 hp0 = make_float4(accP[r][0] + bpv0.x, accP[r][1] + bpv0.y,
                                     accP[r][2] + bpv0.z, accP[r][3] + bpv0.w);
            float4 hp1 = make_float4(accP[r][4] + bpv1.x, accP[r][5] + bpv1.y,
                                     accP[r][6] + bpv1.z, accP[r][7] + bpv1.w);
            float4 os0 = make_float4(accS[r][0] + bsv0.x, accS[r][1] + bsv0.y,
                                     accS[r][2] + bsv0.z, accS[r][3] + bsv0.w);
            float4 os1 = make_float4(accS[r][4] + bsv1.x, accS[r][5] + bsv1.y,
                                     accS[r][6] + bsv1.z, accS[r][7] + bsv1.w);
            *(float4*)&g_h[gr * F + c0] = hp0;
            *(float4*)&g_h[gr * F + c1] = hp1;
            *(float4*)&out[gr * F + c0] = os0;
            *(float4*)&out[gr * F + c1] = os1;
        }
    }
}

// ---------------------------------------------------------------------------
// Edge kernel: warp per edge. Lane l handles 4 features via float4 gather and
// one red.global.add.v4.f32 scatter (4x fewer L2 red-ops than scalar atomics).
// ---------------------------------------------------------------------------
__global__ __launch_bounds__(256) void edge_kernel(const float* __restrict__ efeat,
                                                   const int* __restrict__ src,
                                                   const int* __restrict__ dst) {
    int warp = (blockIdx.x * blockDim.x + threadIdx.x) >> 5;
    int lane = threadIdx.x & 31;
    if (warp >= N_EDGES) return;

    int s   = __ldg(&src[warp]);
    int d   = __ldg(&dst[warp]);
    float w = __ldg(&efeat[warp]);
    float ws = __ldg(&g_wsum[d]);
    float m = __expf(-__fdividef(w, ws));

    float4 v = *(const float4*)&g_h[s * F + lane * 4];
    float* p = &g_agg[d * F + lane * 4];
    asm volatile("red.global.add.v4.f32 [%0], {%1, %2, %3, %4};"
                 :: "l"(p), "f"(m * v.x), "f"(m * v.y), "f"(m * v.z), "f"(m * v.w)
                 : "memory");
}

// ---------------------------------------------------------------------------
// Finalize: out += agg / max(deg, 1)
// ---------------------------------------------------------------------------
__global__ void finalize_kernel(float* __restrict__ out) {
    int i = blockIdx.x * blockDim.x + threadIdx.x;   // float4 index
    if (i < N_NODES * F / 4) {
        int node = i >> 5;
        float inv = 1.0f / fmaxf(g_deg[node], 1.0f);
        float4 a = ((const float4*)g_agg)[i];
        float4 o = ((float4*)out)[i];
        o.x += a.x * inv;
        o.y += a.y * inv;
        o.z += a.z * inv;
        o.w += a.w * inv;
        ((float4*)out)[i] = o;
    }
}

// ---------------------------------------------------------------------------
extern "C" void kernel_launch(void* const* d_in, const int* in_sizes, int n_in,
                              void* d_out, int out_size) {
    const float* feat  = (const float*)d_in[0];
    const float* efeat = (const float*)d_in[1];
    const int*   src   = (const int*)d_in[2];
    const int*   dst   = (const int*)d_in[3];
    const float* Wp    = (const float*)d_in[4];
    const float* bp    = (const float*)d_in[5];
    const float* Ws    = (const float*)d_in[6];
    const float* bs    = (const float*)d_in[7];
    float* out = (float*)d_out;

    zero_kernel<<<(N_NODES * F / 4 + 255) / 256, 256>>>();
    transpose_w<<<(F * F + 255) / 256, 256>>>(Wp, Ws);
    degsum_kernel<<<(N_EDGES + 255) / 256, 256>>>(efeat, dst);
    gemm_dual<<<(N_NODES + TM - 1) / TM, 256>>>(feat, bp, bs, out);
    edge_kernel<<<(N_EDGES * 32) / 256, 256>>>(efeat, src, dst);
    finalize_kernel<<<(N_NODES * F / 4 + 255) / 256, 256>>>(out);
}

// round 2
// speedup vs baseline: 1.0799x; 1.0799x over previous
#include <cuda_runtime.h>
#include <math.h>

#define N_NODES 50000
#define N_EDGES 800000
#define F 128
#define TM 64
#define TK 32

typedef unsigned long long u64;

// Scratch (allocation-free rule: __device__ globals)
__device__ float g_h[N_NODES * F];      // feat @ W_pool^T + b_pool
__device__ float g_agg[N_NODES * F];    // edge-aggregated messages
__device__ float g_wsum[N_NODES];
__device__ float g_deg[N_NODES];
__device__ float g_WpT[F * F];          // W_pool transposed: [k][c]
__device__ float g_WsT[F * F];          // W_self transposed: [k][c]

// ---- packed f32x2 helpers (Blackwell sm_103a; ptxas never auto-fuses) ----
__device__ __forceinline__ u64 pack2(float lo, float hi) {
    u64 r; asm("mov.b64 %0, {%1, %2};" : "=l"(r) : "f"(lo), "f"(hi)); return r;
}
__device__ __forceinline__ u64 fma2(u64 a, u64 b, u64 c) {
    u64 d; asm("fma.rn.f32x2 %0, %1, %2, %3;" : "=l"(d) : "l"(a), "l"(b), "l"(c));
    return d;
}
__device__ __forceinline__ void unpack2(u64 v, float& lo, float& hi) {
    asm("mov.b64 {%0, %1}, %2;" : "=f"(lo), "=f"(hi) : "l"(v));
}

// ---------------------------------------------------------------------------
// Zero scratch accumulators + transpose weights (fused; runs every launch)
// ---------------------------------------------------------------------------
__global__ void zero_transpose_kernel(const float* __restrict__ Wp,
                                      const float* __restrict__ Ws) {
    int i = blockIdx.x * blockDim.x + threadIdx.x;
    if (i < N_NODES * F / 4)
        ((float4*)g_agg)[i] = make_float4(0.f, 0.f, 0.f, 0.f);
    if (i < N_NODES) {
        g_wsum[i] = 0.f;
        g_deg[i]  = 0.f;
    }
    if (i < F * F) {
        int c = i >> 7;
        int k = i & (F - 1);
        g_WpT[k * F + c] = Wp[c * F + k];
        g_WsT[k * F + c] = Ws[c * F + k];
    }
}

// ---------------------------------------------------------------------------
// Per-destination weight sum + degree
// ---------------------------------------------------------------------------
__global__ void degsum_kernel(const float* __restrict__ efeat,
                              const int* __restrict__ dst) {
    int e = blockIdx.x * blockDim.x + threadIdx.x;
    if (e < N_EDGES) {
        int d = dst[e];
        atomicAdd(&g_wsum[d], efeat[e]);
        atomicAdd(&g_deg[d], 1.0f);
    }
}

// ---------------------------------------------------------------------------
// Dual GEMM with packed fp32x2 FMAs:
//   h   = feat @ Wp^T + bp  (to g_h)
//   out = feat @ Ws^T + bs  (to d_out)
// Block = 256 threads, 64x128 tile for BOTH outputs.
// Thread (tr,tc): rows tr*4..+3, col pairs {tc*4..+3} and {64+tc*4..+3},
// accumulated as 4+4 packed f32x2 values per row per output.
// ---------------------------------------------------------------------------
__global__ __launch_bounds__(256, 2) void gemm_dual(const float* __restrict__ feat,
                                                    const float* __restrict__ bp,
                                                    const float* __restrict__ bs,
                                                    float* __restrict__ out) {
    __shared__ float As[TM][TK + 4];   // row stride 36 floats (16B aligned)
    __shared__ float Wps[TK][F];
    __shared__ float Wss[TK][F];

    int tid  = threadIdx.x;
    int row0 = blockIdx.x * TM;
    int tr   = tid >> 4;   // 0..15
    int tc   = tid & 15;   // 0..15

    u64 accP[4][4];        // [row][packed col pair]: pairs (c0c1)(c2c3)(c64_0c64_1)(c64_2c64_3)
    u64 accS[4][4];
    const u64 z = pack2(0.f, 0.f);
#pragma unroll
    for (int r = 0; r < 4; r++)
#pragma unroll
        for (int c = 0; c < 4; c++) { accP[r][c] = z; accS[r][c] = z; }

    for (int kt = 0; kt < F; kt += TK) {
        // Stage A tile: 64 rows x 32 k = 512 float4
#pragma unroll
        for (int j = 0; j < 2; j++) {
            int f4 = tid + j * 256;          // 0..511
            int r  = f4 >> 3;                // 0..63
            int k4 = f4 & 7;                 // 0..7
            int gr = row0 + r;
            float4 v = make_float4(0.f, 0.f, 0.f, 0.f);
            if (gr < N_NODES)
                v = *(const float4*)&feat[gr * F + kt + k4 * 4];
            *(float4*)&As[r][k4 * 4] = v;
        }
        // Stage W tiles: 32 x 128 = 1024 float4 each (coalesced, conflict-free)
#pragma unroll
        for (int j = 0; j < 4; j++) {
            int f4 = tid + j * 256;          // 0..1023
            int k  = f4 >> 5;                // 0..31
            int c4 = f4 & 31;                // 0..31
            *(float4*)&Wps[k][c4 * 4] = *(const float4*)&g_WpT[(kt + k) * F + c4 * 4];
            *(float4*)&Wss[k][c4 * 4] = *(const float4*)&g_WsT[(kt + k) * F + c4 * 4];
        }
        __syncthreads();

#pragma unroll
        for (int kk = 0; kk < TK; kk++) {
            // A scalars (broadcast across the 16 tc lanes of same tr)
            u64 a[4];
#pragma unroll
            for (int r = 0; r < 4; r++) {
                float av = As[tr * 4 + r][kk];
                a[r] = pack2(av, av);
            }
            // Weight pairs: LDS.128 -> two b64 operands each, no repack
            ulonglong2 p0 = *(const ulonglong2*)&Wps[kk][tc * 4];
            ulonglong2 p1 = *(const ulonglong2*)&Wps[kk][64 + tc * 4];
            ulonglong2 s0 = *(const ulonglong2*)&Wss[kk][tc * 4];
            ulonglong2 s1 = *(const ulonglong2*)&Wss[kk][64 + tc * 4];
#pragma unroll
            for (int r = 0; r < 4; r++) {
                accP[r][0] = fma2(a[r], p0.x, accP[r][0]);
                accP[r][1] = fma2(a[r], p0.y, accP[r][1]);
                accP[r][2] = fma2(a[r], p1.x, accP[r][2]);
                accP[r][3] = fma2(a[r], p1.y, accP[r][3]);
                accS[r][0] = fma2(a[r], s0.x, accS[r][0]);
                accS[r][1] = fma2(a[r], s0.y, accS[r][1]);
                accS[r][2] = fma2(a[r], s1.x, accS[r][2]);
                accS[r][3] = fma2(a[r], s1.y, accS[r][3]);
            }
        }
        __syncthreads();
    }

    // Epilogue: unpack, add bias, vectorized stores
    int c0 = tc * 4;
    int c1 = 64 + tc * 4;
    float4 bpv0 = *(const float4*)&bp[c0];
    float4 bpv1 = *(const float4*)&bp[c1];
    float4 bsv0 = *(const float4*)&bs[c0];
    float4 bsv1 = *(const float4*)&bs[c1];
#pragma unroll
    for (int r = 0; r < 4; r++) {
        int gr = row0 + tr * 4 + r;
        if (gr < N_NODES) {
            float4 hp0, hp1, os0, os1;
            unpack2(accP[r][0], hp0.x, hp0.y);
            unpack2(accP[r][1], hp0.z, hp0.w);
            unpack2(accP[r][2], hp1.x, hp1.y);
            unpack2(accP[r][3], hp1.z, hp1.w);
            unpack2(accS[r][0], os0.x, os0.y);
            unpack2(accS[r][1], os0.z, os0.w);
            unpack2(accS[r][2], os1.x, os1.y);
            unpack2(accS[r][3], os1.z, os1.w);
            hp0.x += bpv0.x; hp0.y += bpv0.y; hp0.z += bpv0.z; hp0.w += bpv0.w;
            hp1.x += bpv1.x; hp1.y += bpv1.y; hp1.z += bpv1.z; hp1.w += bpv1.w;
            os0.x += bsv0.x; os0.y += bsv0.y; os0.z += bsv0.z; os0.w += bsv0.w;
            os1.x += bsv1.x; os1.y += bsv1.y; os1.z += bsv1.z; os1.w += bsv1.w;
            *(float4*)&g_h[gr * F + c0] = hp0;
            *(float4*)&g_h[gr * F + c1] = hp1;
            *(float4*)&out[gr * F + c0] = os0;
            *(float4*)&out[gr * F + c1] = os1;
        }
    }
}

// ---------------------------------------------------------------------------
// Edge kernel: warp per edge. Lane l handles 4 features via float4 gather and
// one red.global.add.v4.f32 scatter (4x fewer L2 red-ops than scalar atomics).
// ---------------------------------------------------------------------------
__global__ __launch_bounds__(256) void edge_kernel(const float* __restrict__ efeat,
                                                   const int* __restrict__ src,
                                                   const int* __restrict__ dst) {
    int warp = (blockIdx.x * blockDim.x + threadIdx.x) >> 5;
    int lane = threadIdx.x & 31;
    if (warp >= N_EDGES) return;

    int s   = __ldg(&src[warp]);
    int d   = __ldg(&dst[warp]);
    float w = __ldg(&efeat[warp]);
    float ws = __ldg(&g_wsum[d]);
    float m = __expf(-__fdividef(w, ws));

    float4 v = *(const float4*)&g_h[s * F + lane * 4];
    float* p = &g_agg[d * F + lane * 4];
    asm volatile("red.global.add.v4.f32 [%0], {%1, %2, %3, %4};"
                 :: "l"(p), "f"(m * v.x), "f"(m * v.y), "f"(m * v.z), "f"(m * v.w)
                 : "memory");
}

// ---------------------------------------------------------------------------
// Finalize: out += agg / max(deg, 1)
// ---------------------------------------------------------------------------
__global__ void finalize_kernel(float* __restrict__ out) {
    int i = blockIdx.x * blockDim.x + threadIdx.x;   // float4 index
    if (i < N_NODES * F / 4) {
        int node = i >> 5;
        float inv = 1.0f / fmaxf(g_deg[node], 1.0f);
        float4 a = ((const float4*)g_agg)[i];
        float4 o = ((float4*)out)[i];
        o.x += a.x * inv;
        o.y += a.y * inv;
        o.z += a.z * inv;
        o.w += a.w * inv;
        ((float4*)out)[i] = o;
    }
}

// ---------------------------------------------------------------------------
extern "C" void kernel_launch(void* const* d_in, const int* in_sizes, int n_in,
                              void* d_out, int out_size) {
    const float* feat  = (const float*)d_in[0];
    const float* efeat = (const float*)d_in[1];
    const int*   src   = (const int*)d_in[2];
    const int*   dst   = (const int*)d_in[3];
    const float* Wp    = (const float*)d_in[4];
    const float* bp    = (const float*)d_in[5];
    const float* Ws    = (const float*)d_in[6];
    const float* bs    = (const float*)d_in[7];
    float* out = (float*)d_out;

    zero_transpose_kernel<<<(N_NODES * F / 4 + 255) / 256, 256>>>(Wp, Ws);
    degsum_kernel<<<(N_EDGES + 255) / 256, 256>>>(efeat, dst);
    gemm_dual<<<(N_NODES + TM - 1) / TM, 256>>>(feat, bp, bs, out);
    edge_kernel<<<(N_EDGES * 32) / 256, 256>>>(efeat, src, dst);
    finalize_kernel<<<(N_NODES * F / 4 + 255) / 256, 256>>>(out);
}